// round 14
// baseline (speedup 1.0000x reference)
#include <cuda_runtime.h>
#include <math.h>
#include <stdint.h>

// Problem constants
#define Bb   2
#define Ss   2048
#define Dd   768
#define Hh   12
#define Ii   3072
#define Ll   4
#define MTOK (Bb*Ss)          // 4096 tokens
#define D3   (3*Dd)           // 2304

// ---------------- scratch buffers (device globals; no allocation) -----------
__device__ float g_x   [MTOK*Dd];
__device__ float g_h   [MTOK*Dd];
__device__ float g_qkv [MTOK*D3];
__device__ float g_vals[MTOK*Dd];
__device__ float g_ffn [MTOK*Ii];
__device__ float g_part[3*MTOK*Dd];   // split-K partials (max 3 splits)

// ---------------- tf32 / async helpers ---------------------------------------
__device__ __forceinline__ uint32_t f2tf(float x) {
    uint32_t r; asm("cvt.rna.tf32.f32 %0, %1;" : "=r"(r) : "f"(x)); return r;
}
// round-to-nearest emulation: +half-ulp of the 13 bits tf32 mma truncates
#define RN(u) ((u) + 0x1000u)
__device__ __forceinline__ void mma_tf32(float& c0, float& c1, float& c2, float& c3,
                                         uint32_t a0, uint32_t a1, uint32_t a2, uint32_t a3,
                                         uint32_t b0, uint32_t b1) {
    asm volatile("mma.sync.aligned.m16n8k8.row.col.f32.tf32.tf32.f32 "
                 "{%0,%1,%2,%3}, {%4,%5,%6,%7}, {%8,%9}, {%0,%1,%2,%3};"
                 : "+f"(c0), "+f"(c1), "+f"(c2), "+f"(c3)
                 : "r"(a0), "r"(a1), "r"(a2), "r"(a3), "r"(b0), "r"(b1));
}
__device__ __forceinline__ uint32_t smem_u32(const void* p) {
    uint32_t a;
    asm("{ .reg .u64 t; cvta.to.shared.u64 t, %1; cvt.u32.u64 %0, t; }" : "=r"(a) : "l"(p));
    return a;
}
__device__ __forceinline__ void cp_async16(uint32_t saddr, const void* gptr) {
    asm volatile("cp.async.cg.shared.global [%0], [%1], 16;" :: "r"(saddr), "l"(gptr) : "memory");
}
#define CP_COMMIT() asm volatile("cp.async.commit_group;" ::: "memory")
#define CP_WAIT(n)  asm volatile("cp.async.wait_group %0;" :: "n"(n) : "memory")

// ---------------- LayerNorm -------------------------------------------------
__global__ void ln_kernel(const float* __restrict__ x,
                          const float* __restrict__ w,
                          const float* __restrict__ b,
                          float* __restrict__ out) {
    int row = blockIdx.x;
    const float* xr = x + (size_t)row * Dd;
    float v[3];
    float lsum = 0.f, lsq = 0.f;
#pragma unroll
    for (int i = 0; i < 3; i++) {
        v[i] = xr[threadIdx.x + i * 256];
        lsum += v[i];
        lsq  += v[i] * v[i];
    }
    __shared__ float s1[256], s2[256];
    s1[threadIdx.x] = lsum; s2[threadIdx.x] = lsq;
    __syncthreads();
    for (int off = 128; off > 0; off >>= 1) {
        if (threadIdx.x < off) {
            s1[threadIdx.x] += s1[threadIdx.x + off];
            s2[threadIdx.x] += s2[threadIdx.x + off];
        }
        __syncthreads();
    }
    float mean = s1[0] * (1.f / 768.f);
    float var  = s2[0] * (1.f / 768.f) - mean * mean;
    float inv  = rsqrtf(var + 1e-5f);
#pragma unroll
    for (int i = 0; i < 3; i++) {
        int c = threadIdx.x + i * 256;
        out[(size_t)row * Dd + c] = (v[i] - mean) * inv * w[c] + b[c];
    }
}

// ---------------- TF32 GEMM: cp.async double-buffered, BK=32, dyn smem -------
// 512 thr / 16 warps, BM=BN=128. A smem [2][128][36], B smem [2][32][136].
// Raw fp32 in smem; RN(+0x1000) at fragment load before HW truncation.
#define AST 36
#define BST 136
#define GEMM_SMEM ((2*128*AST + 2*32*BST) * 4)   // 71,680 B

template<bool GELU, bool RES, bool SPLITK>
__global__ __launch_bounds__(512, 2) void gemm_tf32(int M, int N, int K,
                               const float* __restrict__ A,
                               const float* __restrict__ Bm,
                               const float* __restrict__ bias,
                               const float* __restrict__ res,
                               float* __restrict__ C) {
    extern __shared__ uint32_t gsm[];
    uint32_t* Asm = gsm;                 // [2][128][AST]
    uint32_t* Bsm = gsm + 2 * 128 * AST; // [2][32][BST]
    int tid  = threadIdx.x;
    int lane = tid & 31, wid = tid >> 5;
    int wm = (wid >> 2) * 32;
    int wn = (wid & 3) * 32;
    int qr = lane >> 2, qc = lane & 3;
    int row0 = blockIdx.y * 128, col0 = blockIdx.x * 128;

    int Ks = K;
    const float* Ab = A;
    const float* Bb2 = Bm;
    if (SPLITK) {
        Ks = K / gridDim.z;
        int koff = blockIdx.z * Ks;
        Ab  = A + koff;
        Bb2 = Bm + (size_t)koff * N;
        C   = C + (size_t)blockIdx.z * M * N;
    }

    // loader coords: 2 cp.async16 per thread for A and for B per tile
    int aI0 = tid * 2, aI1 = tid * 2 + 1;
    int aRow0 = aI0 >> 3, aSeg0 = (aI0 & 7) * 4;
    int aRow1 = aI1 >> 3, aSeg1 = (aI1 & 7) * 4;
    int bRow0 = aI0 >> 5, bSeg0 = (aI0 & 31) * 4;
    int bRow1 = aI1 >> 5, bSeg1 = (aI1 & 31) * 4;
    uint32_t sA = smem_u32(Asm), sB = smem_u32(Bsm);
    const float* aG0 = Ab + (size_t)(row0 + aRow0) * K + aSeg0;
    const float* aG1 = Ab + (size_t)(row0 + aRow1) * K + aSeg1;
    const float* bG0 = Bb2 + (size_t)bRow0 * N + col0 + bSeg0;
    const float* bG1 = Bb2 + (size_t)bRow1 * N + col0 + bSeg1;

    float acc[2][4][4] = {};

    const int nT = Ks / 32;
    cp_async16(sA + (aRow0 * AST + aSeg0) * 4, aG0);
    cp_async16(sA + (aRow1 * AST + aSeg1) * 4, aG1);
    cp_async16(sB + (bRow0 * BST + bSeg0) * 4, bG0);
    cp_async16(sB + (bRow1 * BST + bSeg1) * 4, bG1);
    CP_COMMIT();

    for (int t = 0; t < nT; t++) {
        int cur = t & 1;
        if (t + 1 < nT) {
            int buf = cur ^ 1;
            int k0 = (t + 1) * 32;
            cp_async16(sA + ((buf * 128 + aRow0) * AST + aSeg0) * 4, aG0 + k0);
            cp_async16(sA + ((buf * 128 + aRow1) * AST + aSeg1) * 4, aG1 + k0);
            cp_async16(sB + ((buf * 32 + bRow0) * BST + bSeg0) * 4, bG0 + (size_t)k0 * N);
            cp_async16(sB + ((buf * 32 + bRow1) * BST + bSeg1) * 4, bG1 + (size_t)k0 * N);
            CP_COMMIT();
            CP_WAIT(1);
        } else {
            CP_WAIT(0);
        }
        __syncthreads();
        const uint32_t* Ac = Asm + cur * 128 * AST;
        const uint32_t* Bc = Bsm + cur * 32 * BST;
#pragma unroll
        for (int ks = 0; ks < 32; ks += 8) {
            uint32_t af[2][4], bf[4][2];
#pragma unroll
            for (int i = 0; i < 2; i++) {
                int m = wm + i * 16 + qr;
                af[i][0] = RN(Ac[m * AST + ks + qc]);
                af[i][1] = RN(Ac[(m + 8) * AST + ks + qc]);
                af[i][2] = RN(Ac[m * AST + ks + qc + 4]);
                af[i][3] = RN(Ac[(m + 8) * AST + ks + qc + 4]);
            }
#pragma unroll
            for (int j = 0; j < 4; j++) {
                int n = wn + j * 8 + qr;
                bf[j][0] = RN(Bc[(ks + qc) * BST + n]);
                bf[j][1] = RN(Bc[(ks + qc + 4) * BST + n]);
            }
#pragma unroll
            for (int i = 0; i < 2; i++)
#pragma unroll
                for (int j = 0; j < 4; j++)
                    mma_tf32(acc[i][j][0], acc[i][j][1], acc[i][j][2], acc[i][j][3],
                             af[i][0], af[i][1], af[i][2], af[i][3],
                             bf[j][0], bf[j][1]);
        }
        __syncthreads();
    }
#pragma unroll
    for (int i = 0; i < 2; i++) {
        int r0 = row0 + wm + i * 16 + qr;
        int r1 = r0 + 8;
#pragma unroll
        for (int j = 0; j < 4; j++) {
            int c0 = col0 + wn + j * 8 + qc * 2;
            float v0 = acc[i][j][0];
            float v1 = acc[i][j][1];
            float v2 = acc[i][j][2];
            float v3 = acc[i][j][3];
            if (!SPLITK) {
                v0 += bias[c0]; v1 += bias[c0 + 1];
                v2 += bias[c0]; v3 += bias[c0 + 1];
                if (GELU) {
                    v0 = 0.5f * v0 * (1.0f + erff(v0 * 0.70710678f));
                    v1 = 0.5f * v1 * (1.0f + erff(v1 * 0.70710678f));
                    v2 = 0.5f * v2 * (1.0f + erff(v2 * 0.70710678f));
                    v3 = 0.5f * v3 * (1.0f + erff(v3 * 0.70710678f));
                }
                if (RES) {
                    float2 r0v = *(const float2*)(res + (size_t)r0 * N + c0);
                    float2 r1v = *(const float2*)(res + (size_t)r1 * N + c0);
                    v0 += r0v.x; v1 += r0v.y; v2 += r1v.x; v3 += r1v.y;
                }
            }
            *(float2*)(C + (size_t)r0 * N + c0) = make_float2(v0, v1);
            *(float2*)(C + (size_t)r1 * N + c0) = make_float2(v2, v3);
        }
    }
}

// ---------------- split-K reduce: out = res + bias + sum(parts) --------------
template<int NS>
__global__ void reduce_kernel(const float* __restrict__ parts,
                              const float* __restrict__ bias,
                              const float* __restrict__ res,
                              float* __restrict__ out, int N, int total) {
    int i = blockIdx.x * blockDim.x + threadIdx.x;
    int i4 = i * 4;
    if (i4 >= total) return;
    int col = i4 % N;
    float4 b = *(const float4*)(bias + col);
    float4 r = *(const float4*)(res + i4);
    float4 s = make_float4(r.x + b.x, r.y + b.y, r.z + b.z, r.w + b.w);
#pragma unroll
    for (int z = 0; z < NS; z++) {
        float4 p = *(const float4*)(parts + (size_t)z * total + i4);
        s.x += p.x; s.y += p.y; s.z += p.z; s.w += p.w;
    }
    *(float4*)(out + i4) = s;
}

// ---------------- fused flash attention: cp.async double-buffered KV ---------
#define TSV  32
#define KST  68
#define VST  72
#define PST  68
#define FLASH_SMEM ((2*TSV*KST + 2*TSV*VST + 4*16*PST) * 4)   // 53,248 B

__global__ __launch_bounds__(128, 4) void flash_tf32(const float* __restrict__ qkv,
                                                     float* __restrict__ vals) {
    extern __shared__ uint32_t sm[];
    uint32_t* Ks   = sm;
    uint32_t* Vs   = sm + 2 * TSV * KST;
    uint32_t* Pall = Vs + 2 * TSV * VST;

    int tid = threadIdx.x, lane = tid & 31, wid = tid >> 5;
    int qr = lane >> 2, qc = lane & 3;
    int z = blockIdx.y, b = z / Hh, h = z - b * Hh;
    const float* Qb = qkv + (size_t)b * Ss * D3 + h * 192;
    const float* Kb = Qb + 64;
    const float* Vb = Qb + 128;
    int row0 = blockIdx.x * 64;
    uint32_t* Pw = Pall + wid * 16 * PST;
    int wrow = wid * 16;

    uint32_t sKs = smem_u32(Ks), sVs = smem_u32(Vs);

    {
#pragma unroll
        for (int k = 0; k < 4; k++) {
            int i = tid + k * 128;
            int t = i >> 4, d = (i & 15) << 2;
            cp_async16(sKs + (t * KST + d) * 4, Kb + (size_t)t * D3 + d);
            cp_async16(sVs + (t * VST + d) * 4, Vb + (size_t)t * D3 + d);
        }
        CP_COMMIT();
    }

    for (int i = tid; i < 1024; i += 128) {
        int t = i >> 4, d = (i & 15) << 2;
        float4 q4 = *(const float4*)(Qb + (size_t)(row0 + t) * D3 + d);
        uint32_t* dst = Pall + t * PST + d;
        dst[0] = f2tf(q4.x * 0.125f);
        dst[1] = f2tf(q4.y * 0.125f);
        dst[2] = f2tf(q4.z * 0.125f);
        dst[3] = f2tf(q4.w * 0.125f);
    }
    __syncthreads();
    uint32_t qa[8][4];
#pragma unroll
    for (int kc = 0; kc < 8; kc++) {
        qa[kc][0] = Pall[(wrow + qr)     * PST + kc * 8 + qc];
        qa[kc][1] = Pall[(wrow + qr + 8) * PST + kc * 8 + qc];
        qa[kc][2] = Pall[(wrow + qr)     * PST + kc * 8 + qc + 4];
        qa[kc][3] = Pall[(wrow + qr + 8) * PST + kc * 8 + qc + 4];
    }
    __syncthreads();

    float m0 = -1e30f, m1 = -1e30f, l0 = 0.f, l1 = 0.f;
    float o[8][4] = {};

    const int NIT = Ss / TSV;   // 64
    for (int it = 0; it < NIT; it++) {
        int cur = it & 1;
        if (it + 1 < NIT) {
            int kv = (it + 1) * TSV;
            int buf = cur ^ 1;
#pragma unroll
            for (int k = 0; k < 4; k++) {
                int i = tid + k * 128;
                int t = i >> 4, d = (i & 15) << 2;
                cp_async16(sKs + (buf * TSV * KST + t * KST + d) * 4,
                           Kb + (size_t)(kv + t) * D3 + d);
                cp_async16(sVs + (buf * TSV * VST + t * VST + d) * 4,
                           Vb + (size_t)(kv + t) * D3 + d);
            }
            CP_COMMIT();
            CP_WAIT(1);
        } else {
            CP_WAIT(0);
        }
        __syncthreads();
        uint32_t* Kc = Ks + cur * TSV * KST;
        uint32_t* Vc = Vs + cur * TSV * VST;

        float s[4][4];
#pragma unroll
        for (int j = 0; j < 4; j++) {
            s[j][0] = s[j][1] = s[j][2] = s[j][3] = 0.f;
#pragma unroll
            for (int kc = 0; kc < 8; kc++) {
                uint32_t b0 = Kc[(j * 8 + qr) * KST + kc * 8 + qc];
                uint32_t b1 = Kc[(j * 8 + qr) * KST + kc * 8 + qc + 4];
                mma_tf32(s[j][0], s[j][1], s[j][2], s[j][3],
                         qa[kc][0], qa[kc][1], qa[kc][2], qa[kc][3], b0, b1);
            }
        }

        float tm0 = -1e30f, tm1 = -1e30f;
#pragma unroll
        for (int j = 0; j < 4; j++) {
            tm0 = fmaxf(tm0, fmaxf(s[j][0], s[j][1]));
            tm1 = fmaxf(tm1, fmaxf(s[j][2], s[j][3]));
        }
        tm0 = fmaxf(tm0, __shfl_xor_sync(0xffffffffu, tm0, 1));
        tm0 = fmaxf(tm0, __shfl_xor_sync(0xffffffffu, tm0, 2));
        tm1 = fmaxf(tm1, __shfl_xor_sync(0xffffffffu, tm1, 1));
        tm1 = fmaxf(tm1, __shfl_xor_sync(0xffffffffu, tm1, 2));
        float mn0 = fmaxf(m0, tm0), mn1 = fmaxf(m1, tm1);
        float sc0 = __expf(m0 - mn0), sc1 = __expf(m1 - mn1);
        m0 = mn0; m1 = mn1;

        float ls0 = 0.f, ls1 = 0.f;
#pragma unroll
        for (int j = 0; j < 4; j++) {
            float p0 = __expf(s[j][0] - m0);
            float p1 = __expf(s[j][1] - m0);
            float p2 = __expf(s[j][2] - m1);
            float p3 = __expf(s[j][3] - m1);
            ls0 += p0 + p1; ls1 += p2 + p3;
            uint2 u0; u0.x = f2tf(p0); u0.y = f2tf(p1);
            uint2 u1; u1.x = f2tf(p2); u1.y = f2tf(p3);
            *(uint2*)(Pw + qr * PST + j * 8 + qc * 2)       = u0;
            *(uint2*)(Pw + (qr + 8) * PST + j * 8 + qc * 2) = u1;
        }
        ls0 += __shfl_xor_sync(0xffffffffu, ls0, 1);
        ls0 += __shfl_xor_sync(0xffffffffu, ls0, 2);
        ls1 += __shfl_xor_sync(0xffffffffu, ls1, 1);
        ls1 += __shfl_xor_sync(0xffffffffu, ls1, 2);
        l0 = l0 * sc0 + ls0;
        l1 = l1 * sc1 + ls1;
#pragma unroll
        for (int j = 0; j < 8; j++) {
            o[j][0] *= sc0; o[j][1] *= sc0; o[j][2] *= sc1; o[j][3] *= sc1;
        }
        __syncwarp();

#pragma unroll
        for (int kc = 0; kc < 4; kc++) {
            uint32_t a0 = Pw[qr * PST + kc * 8 + qc];
            uint32_t a1 = Pw[(qr + 8) * PST + kc * 8 + qc];
            uint32_t a2 = Pw[qr * PST + kc * 8 + qc + 4];
            uint32_t a3 = Pw[(qr + 8) * PST + kc * 8 + qc + 4];
#pragma unroll
            for (int j = 0; j < 8; j++) {
                uint32_t b0 = Vc[(kc * 8 + qc) * VST + j * 8 + qr];
                uint32_t b1 = Vc[(kc * 8 + qc + 4) * VST + j * 8 + qr];
                mma_tf32(o[j][0], o[j][1], o[j][2], o[j][3], a0, a1, a2, a3, b0, b1);
            }
        }
        __syncthreads();
    }

    float inv0 = 1.f / l0, inv1 = 1.f / l1;
    size_t r0 = (size_t)b * Ss + row0 + wrow + qr;
    size_t r1 = r0 + 8;
#pragma unroll
    for (int j = 0; j < 8; j++) {
        int c0 = h * 64 + j * 8 + qc * 2;
        *(float2*)(vals + r0 * Dd + c0) = make_float2(o[j][0] * inv0, o[j][1] * inv0);
        *(float2*)(vals + r1 * Dd + c0) = make_float2(o[j][2] * inv1, o[j][3] * inv1);
    }
}

// ---------------- host launch ----------------------------------------------
extern "C" void kernel_launch(void* const* d_in, const int* in_sizes, int n_in,
                              void* d_out, int out_size) {
    const float* x     = (const float*)d_in[0];
    const float* qkv_w = (const float*)d_in[1];
    const float* qkv_b = (const float*)d_in[2];
    const float* out_w = (const float*)d_in[3];
    const float* out_b = (const float*)d_in[4];
    const float* ln1_w = (const float*)d_in[5];
    const float* ln1_b = (const float*)d_in[6];
    const float* fc1_w = (const float*)d_in[7];
    const float* fc1_b = (const float*)d_in[8];
    const float* fc2_w = (const float*)d_in[9];
    const float* fc2_b = (const float*)d_in[10];
    const float* ln2_w = (const float*)d_in[11];
    const float* ln2_b = (const float*)d_in[12];

    float *xb, *hb, *qkvb, *vb, *fb, *pb;
    cudaGetSymbolAddress((void**)&xb,  g_x);
    cudaGetSymbolAddress((void**)&hb,  g_h);
    cudaGetSymbolAddress((void**)&qkvb,g_qkv);
    cudaGetSymbolAddress((void**)&vb,  g_vals);
    cudaGetSymbolAddress((void**)&fb,  g_ffn);
    cudaGetSymbolAddress((void**)&pb,  g_part);

    cudaFuncSetAttribute(flash_tf32, cudaFuncAttributeMaxDynamicSharedMemorySize, FLASH_SMEM);
    cudaFuncSetAttribute(gemm_tf32<false, false, false>,
                         cudaFuncAttributeMaxDynamicSharedMemorySize, GEMM_SMEM);
    cudaFuncSetAttribute(gemm_tf32<true, false, false>,
                         cudaFuncAttributeMaxDynamicSharedMemorySize, GEMM_SMEM);
    cudaFuncSetAttribute(gemm_tf32<false, false, true>,
                         cudaFuncAttributeMaxDynamicSharedMemorySize, GEMM_SMEM);

    const int total = MTOK * Dd;
    const int redBlocks = (total / 4 + 255) / 256;

    for (int l = 0; l < Ll; l++) {
        const float* qw  = qkv_w + (size_t)l * Dd * D3;
        const float* qbb = qkv_b + (size_t)l * D3;
        const float* ow  = out_w + (size_t)l * Dd * Dd;
        const float* ob  = out_b + (size_t)l * Dd;
        const float* l1w = ln1_w + (size_t)l * Dd;
        const float* l1b = ln1_b + (size_t)l * Dd;
        const float* f1w = fc1_w + (size_t)l * Dd * Ii;
        const float* f1b = fc1_b + (size_t)l * Ii;
        const float* f2w = fc2_w + (size_t)l * Ii * Dd;
        const float* f2b = fc2_b + (size_t)l * Dd;
        const float* l2w = ln2_w + (size_t)l * Dd;
        const float* l2b = ln2_b + (size_t)l * Dd;

        const float* xin = (l == 0) ? x : xb;
        float* xout_ffn  = (l == Ll - 1) ? (float*)d_out : xb;

        ln_kernel<<<MTOK, 256>>>(xin, l1w, l1b, hb);
        gemm_tf32<false, false, false><<<dim3(D3 / 128, MTOK / 128), 512, GEMM_SMEM>>>(
            MTOK, D3, Dd, hb, qw, qbb, nullptr, qkvb);
        flash_tf32<<<dim3(Ss / 64, Bb * Hh), 128, FLASH_SMEM>>>(qkvb, vb);
        gemm_tf32<false, false, true><<<dim3(Dd / 128, MTOK / 128, 3), 512, GEMM_SMEM>>>(
            MTOK, Dd, Dd, vb, ow, nullptr, nullptr, pb);
        reduce_kernel<3><<<redBlocks, 256>>>(pb, ob, xin, xb, Dd, total);
        ln_kernel<<<MTOK, 256>>>(xb, l2w, l2b, hb);
        gemm_tf32<true, false, false><<<dim3(Ii / 128, MTOK / 128), 512, GEMM_SMEM>>>(
            MTOK, Ii, Dd, hb, f1w, f1b, nullptr, fb);
        gemm_tf32<false, false, true><<<dim3(Dd / 128, MTOK / 128, 3), 512, GEMM_SMEM>>>(
            MTOK, Dd, Ii, fb, f2w, nullptr, nullptr, pb);
        reduce_kernel<3><<<redBlocks, 256>>>(pb, f2b, xb, xout_ffn, Dd, total);
    }
}

// round 15
// speedup vs baseline: 1.0177x; 1.0177x over previous
#include <cuda_runtime.h>
#include <math.h>
#include <stdint.h>

// Problem constants
#define Bb   2
#define Ss   2048
#define Dd   768
#define Hh   12
#define Ii   3072
#define Ll   4
#define MTOK (Bb*Ss)          // 4096 tokens
#define D3   (3*Dd)           // 2304

// ---------------- scratch buffers (device globals; no allocation) -----------
__device__ float g_x   [MTOK*Dd];
__device__ float g_h   [MTOK*Dd];
__device__ float g_qkv [MTOK*D3];
__device__ float g_vals[MTOK*Dd];
__device__ float g_ffn [MTOK*Ii];
__device__ float g_part[3*MTOK*Dd];   // split-K partials (max 3 splits)

// ---------------- tf32 / async helpers ---------------------------------------
__device__ __forceinline__ uint32_t f2tf(float x) {
    uint32_t r; asm("cvt.rna.tf32.f32 %0, %1;" : "=r"(r) : "f"(x)); return r;
}
// round-to-nearest emulation: +half-ulp of the 13 bits tf32 mma truncates
#define RN(u) ((u) + 0x1000u)
__device__ __forceinline__ void mma_tf32(float& c0, float& c1, float& c2, float& c3,
                                         uint32_t a0, uint32_t a1, uint32_t a2, uint32_t a3,
                                         uint32_t b0, uint32_t b1) {
    asm volatile("mma.sync.aligned.m16n8k8.row.col.f32.tf32.tf32.f32 "
                 "{%0,%1,%2,%3}, {%4,%5,%6,%7}, {%8,%9}, {%0,%1,%2,%3};"
                 : "+f"(c0), "+f"(c1), "+f"(c2), "+f"(c3)
                 : "r"(a0), "r"(a1), "r"(a2), "r"(a3), "r"(b0), "r"(b1));
}
__device__ __forceinline__ uint32_t smem_u32(const void* p) {
    uint32_t a;
    asm("{ .reg .u64 t; cvta.to.shared.u64 t, %1; cvt.u32.u64 %0, t; }" : "=r"(a) : "l"(p));
    return a;
}
__device__ __forceinline__ void cp_async16(uint32_t saddr, const void* gptr) {
    asm volatile("cp.async.cg.shared.global [%0], [%1], 16;" :: "r"(saddr), "l"(gptr) : "memory");
}
#define CP_COMMIT() asm volatile("cp.async.commit_group;" ::: "memory")
#define CP_WAIT(n)  asm volatile("cp.async.wait_group %0;" :: "n"(n) : "memory")

// ---------------- LayerNorm (standalone: only layer 0's LN1) -----------------
__global__ void ln_kernel(const float* __restrict__ x,
                          const float* __restrict__ w,
                          const float* __restrict__ b,
                          float* __restrict__ out) {
    int row = blockIdx.x;
    const float* xr = x + (size_t)row * Dd;
    float v[3];
    float lsum = 0.f, lsq = 0.f;
#pragma unroll
    for (int i = 0; i < 3; i++) {
        v[i] = xr[threadIdx.x + i * 256];
        lsum += v[i];
        lsq  += v[i] * v[i];
    }
    __shared__ float s1[256], s2[256];
    s1[threadIdx.x] = lsum; s2[threadIdx.x] = lsq;
    __syncthreads();
    for (int off = 128; off > 0; off >>= 1) {
        if (threadIdx.x < off) {
            s1[threadIdx.x] += s1[threadIdx.x + off];
            s2[threadIdx.x] += s2[threadIdx.x + off];
        }
        __syncthreads();
    }
    float mean = s1[0] * (1.f / 768.f);
    float var  = s2[0] * (1.f / 768.f) - mean * mean;
    float inv  = rsqrtf(var + 1e-5f);
#pragma unroll
    for (int i = 0; i < 3; i++) {
        int c = threadIdx.x + i * 256;
        out[(size_t)row * Dd + c] = (v[i] - mean) * inv * w[c] + b[c];
    }
}

// ---------------- fused split-K reduce + residual + LayerNorm ----------------
// x = res + bias + sum(parts); h = LN(x). One block per token row.
template<int NS>
__global__ void reduce_ln_kernel(const float* __restrict__ parts,
                                 const float* __restrict__ bias,
                                 const float* __restrict__ res,
                                 const float* __restrict__ lnw,
                                 const float* __restrict__ lnb,
                                 float* __restrict__ xout,
                                 float* __restrict__ hout) {
    int row = blockIdx.x;
    size_t base = (size_t)row * Dd;
    float v[3];
    float lsum = 0.f, lsq = 0.f;
#pragma unroll
    for (int i = 0; i < 3; i++) {
        int c = threadIdx.x + i * 256;
        float s = res[base + c] + bias[c];
#pragma unroll
        for (int z = 0; z < NS; z++)
            s += parts[(size_t)z * (MTOK * Dd) + base + c];
        v[i] = s;
        lsum += s;
        lsq  += s * s;
    }
    __shared__ float s1[256], s2[256];
    s1[threadIdx.x] = lsum; s2[threadIdx.x] = lsq;
    __syncthreads();
    for (int off = 128; off > 0; off >>= 1) {
        if (threadIdx.x < off) {
            s1[threadIdx.x] += s1[threadIdx.x + off];
            s2[threadIdx.x] += s2[threadIdx.x + off];
        }
        __syncthreads();
    }
    float mean = s1[0] * (1.f / 768.f);
    float var  = s2[0] * (1.f / 768.f) - mean * mean;
    float inv  = rsqrtf(var + 1e-5f);
#pragma unroll
    for (int i = 0; i < 3; i++) {
        int c = threadIdx.x + i * 256;
        xout[base + c] = v[i];
        hout[base + c] = (v[i] - mean) * inv * lnw[c] + lnb[c];
    }
}

// ---------------- plain split-K reduce (last layer's FFN -> d_out) -----------
template<int NS>
__global__ void reduce_kernel(const float* __restrict__ parts,
                              const float* __restrict__ bias,
                              const float* __restrict__ res,
                              float* __restrict__ out, int N, int total) {
    int i = blockIdx.x * blockDim.x + threadIdx.x;
    int i4 = i * 4;
    if (i4 >= total) return;
    int col = i4 % N;
    float4 b = *(const float4*)(bias + col);
    float4 r = *(const float4*)(res + i4);
    float4 s = make_float4(r.x + b.x, r.y + b.y, r.z + b.z, r.w + b.w);
#pragma unroll
    for (int z = 0; z < NS; z++) {
        float4 p = *(const float4*)(parts + (size_t)z * total + i4);
        s.x += p.x; s.y += p.y; s.z += p.z; s.w += p.w;
    }
    *(float4*)(out + i4) = s;
}

// ---------------- TF32 GEMM: cp.async double-buffered (R13 config) -----------
// BM=BN=128, BK=16, 512 thr / 16 warps. A smem [128][20], B smem [16][136].
// Raw fp32 in smem; RN(+0x1000) at fragment load before HW truncation.
#define AST 20
#define BST 136
template<bool GELU, bool RES, bool SPLITK>
__global__ __launch_bounds__(512, 2) void gemm_tf32(int M, int N, int K,
                               const float* __restrict__ A,
                               const float* __restrict__ Bm,
                               const float* __restrict__ bias,
                               const float* __restrict__ res,
                               float* __restrict__ C) {
    __shared__ uint32_t As[2][128][AST];
    __shared__ uint32_t Bs[2][16][BST];
    int tid  = threadIdx.x;
    int lane = tid & 31, wid = tid >> 5;
    int wm = (wid >> 2) * 32;
    int wn = (wid & 3) * 32;
    int qr = lane >> 2, qc = lane & 3;
    int row0 = blockIdx.y * 128, col0 = blockIdx.x * 128;

    int Ks = K;
    const float* Ab = A;
    const float* Bb2 = Bm;
    if (SPLITK) {
        Ks = K / gridDim.z;
        int koff = blockIdx.z * Ks;
        Ab  = A + koff;
        Bb2 = Bm + (size_t)koff * N;
        C   = C + (size_t)blockIdx.z * M * N;
    }

    int aRow = tid >> 2, aSeg = (tid & 3) * 4;
    int bRow = tid >> 5, bSeg = (tid & 31) * 4;
    uint32_t sA = smem_u32(As), sB = smem_u32(Bs);
    const float* aG = Ab + (size_t)(row0 + aRow) * K + aSeg;
    const float* bG = Bb2 + (size_t)bRow * N + col0 + bSeg;

    float acc[2][4][4] = {};

    const int nT = Ks / 16;
    cp_async16(sA + ((0 * 128 + aRow) * AST + aSeg) * 4, aG);
    cp_async16(sB + ((0 * 16 + bRow) * BST + bSeg) * 4, bG);
    CP_COMMIT();

    for (int t = 0; t < nT; t++) {
        int cur = t & 1;
        if (t + 1 < nT) {
            int buf = cur ^ 1;
            int k0 = (t + 1) * 16;
            cp_async16(sA + ((buf * 128 + aRow) * AST + aSeg) * 4, aG + k0);
            cp_async16(sB + ((buf * 16 + bRow) * BST + bSeg) * 4, bG + (size_t)k0 * N);
            CP_COMMIT();
            CP_WAIT(1);
        } else {
            CP_WAIT(0);
        }
        __syncthreads();
#pragma unroll
        for (int ks = 0; ks < 16; ks += 8) {
            uint32_t af[2][4], bf[4][2];
#pragma unroll
            for (int i = 0; i < 2; i++) {
                int m = wm + i * 16 + qr;
                af[i][0] = RN(As[cur][m][ks + qc]);
                af[i][1] = RN(As[cur][m + 8][ks + qc]);
                af[i][2] = RN(As[cur][m][ks + qc + 4]);
                af[i][3] = RN(As[cur][m + 8][ks + qc + 4]);
            }
#pragma unroll
            for (int j = 0; j < 4; j++) {
                int n = wn + j * 8 + qr;
                bf[j][0] = RN(Bs[cur][ks + qc][n]);
                bf[j][1] = RN(Bs[cur][ks + qc + 4][n]);
            }
#pragma unroll
            for (int i = 0; i < 2; i++)
#pragma unroll
                for (int j = 0; j < 4; j++)
                    mma_tf32(acc[i][j][0], acc[i][j][1], acc[i][j][2], acc[i][j][3],
                             af[i][0], af[i][1], af[i][2], af[i][3],
                             bf[j][0], bf[j][1]);
        }
        __syncthreads();
    }
#pragma unroll
    for (int i = 0; i < 2; i++) {
        int r0 = row0 + wm + i * 16 + qr;
        int r1 = r0 + 8;
#pragma unroll
        for (int j = 0; j < 4; j++) {
            int c0 = col0 + wn + j * 8 + qc * 2;
            float v0 = acc[i][j][0];
            float v1 = acc[i][j][1];
            float v2 = acc[i][j][2];
            float v3 = acc[i][j][3];
            if (!SPLITK) {
                v0 += bias[c0]; v1 += bias[c0 + 1];
                v2 += bias[c0]; v3 += bias[c0 + 1];
                if (GELU) {
                    v0 = 0.5f * v0 * (1.0f + erff(v0 * 0.70710678f));
                    v1 = 0.5f * v1 * (1.0f + erff(v1 * 0.70710678f));
                    v2 = 0.5f * v2 * (1.0f + erff(v2 * 0.70710678f));
                    v3 = 0.5f * v3 * (1.0f + erff(v3 * 0.70710678f));
                }
                if (RES) {
                    float2 r0v = *(const float2*)(res + (size_t)r0 * N + c0);
                    float2 r1v = *(const float2*)(res + (size_t)r1 * N + c0);
                    v0 += r0v.x; v1 += r0v.y; v2 += r1v.x; v3 += r1v.y;
                }
            }
            *(float2*)(C + (size_t)r0 * N + c0) = make_float2(v0, v1);
            *(float2*)(C + (size_t)r1 * N + c0) = make_float2(v2, v3);
        }
    }
}

// ---------------- fused flash attention: cp.async double-buffered KV ---------
#define TSV  32
#define KST  68
#define VST  72
#define PST  68
#define FLASH_SMEM ((2*TSV*KST + 2*TSV*VST + 4*16*PST) * 4)   // 53,248 B

__global__ __launch_bounds__(128, 4) void flash_tf32(const float* __restrict__ qkv,
                                                     float* __restrict__ vals) {
    extern __shared__ uint32_t sm[];
    uint32_t* Ks   = sm;
    uint32_t* Vs   = sm + 2 * TSV * KST;
    uint32_t* Pall = Vs + 2 * TSV * VST;

    int tid = threadIdx.x, lane = tid & 31, wid = tid >> 5;
    int qr = lane >> 2, qc = lane & 3;
    int z = blockIdx.y, b = z / Hh, h = z - b * Hh;
    const float* Qb = qkv + (size_t)b * Ss * D3 + h * 192;
    const float* Kb = Qb + 64;
    const float* Vb = Qb + 128;
    int row0 = blockIdx.x * 64;
    uint32_t* Pw = Pall + wid * 16 * PST;
    int wrow = wid * 16;

    uint32_t sKs = smem_u32(Ks), sVs = smem_u32(Vs);

    {
#pragma unroll
        for (int k = 0; k < 4; k++) {
            int i = tid + k * 128;
            int t = i >> 4, d = (i & 15) << 2;
            cp_async16(sKs + (t * KST + d) * 4, Kb + (size_t)t * D3 + d);
            cp_async16(sVs + (t * VST + d) * 4, Vb + (size_t)t * D3 + d);
        }
        CP_COMMIT();
    }

    for (int i = tid; i < 1024; i += 128) {
        int t = i >> 4, d = (i & 15) << 2;
        float4 q4 = *(const float4*)(Qb + (size_t)(row0 + t) * D3 + d);
        uint32_t* dst = Pall + t * PST + d;
        dst[0] = f2tf(q4.x * 0.125f);
        dst[1] = f2tf(q4.y * 0.125f);
        dst[2] = f2tf(q4.z * 0.125f);
        dst[3] = f2tf(q4.w * 0.125f);
    }
    __syncthreads();
    uint32_t qa[8][4];
#pragma unroll
    for (int kc = 0; kc < 8; kc++) {
        qa[kc][0] = Pall[(wrow + qr)     * PST + kc * 8 + qc];
        qa[kc][1] = Pall[(wrow + qr + 8) * PST + kc * 8 + qc];
        qa[kc][2] = Pall[(wrow + qr)     * PST + kc * 8 + qc + 4];
        qa[kc][3] = Pall[(wrow + qr + 8) * PST + kc * 8 + qc + 4];
    }
    __syncthreads();

    float m0 = -1e30f, m1 = -1e30f, l0 = 0.f, l1 = 0.f;
    float o[8][4] = {};

    const int NIT = Ss / TSV;   // 64
    for (int it = 0; it < NIT; it++) {
        int cur = it & 1;
        if (it + 1 < NIT) {
            int kv = (it + 1) * TSV;
            int buf = cur ^ 1;
#pragma unroll
            for (int k = 0; k < 4; k++) {
                int i = tid + k * 128;
                int t = i >> 4, d = (i & 15) << 2;
                cp_async16(sKs + (buf * TSV * KST + t * KST + d) * 4,
                           Kb + (size_t)(kv + t) * D3 + d);
                cp_async16(sVs + (buf * TSV * VST + t * VST + d) * 4,
                           Vb + (size_t)(kv + t) * D3 + d);
            }
            CP_COMMIT();
            CP_WAIT(1);
        } else {
            CP_WAIT(0);
        }
        __syncthreads();
        uint32_t* Kc = Ks + cur * TSV * KST;
        uint32_t* Vc = Vs + cur * TSV * VST;

        float s[4][4];
#pragma unroll
        for (int j = 0; j < 4; j++) {
            s[j][0] = s[j][1] = s[j][2] = s[j][3] = 0.f;
#pragma unroll
            for (int kc = 0; kc < 8; kc++) {
                uint32_t b0 = Kc[(j * 8 + qr) * KST + kc * 8 + qc];
                uint32_t b1 = Kc[(j * 8 + qr) * KST + kc * 8 + qc + 4];
                mma_tf32(s[j][0], s[j][1], s[j][2], s[j][3],
                         qa[kc][0], qa[kc][1], qa[kc][2], qa[kc][3], b0, b1);
            }
        }

        float tm0 = -1e30f, tm1 = -1e30f;
#pragma unroll
        for (int j = 0; j < 4; j++) {
            tm0 = fmaxf(tm0, fmaxf(s[j][0], s[j][1]));
            tm1 = fmaxf(tm1, fmaxf(s[j][2], s[j][3]));
        }
        tm0 = fmaxf(tm0, __shfl_xor_sync(0xffffffffu, tm0, 1));
        tm0 = fmaxf(tm0, __shfl_xor_sync(0xffffffffu, tm0, 2));
        tm1 = fmaxf(tm1, __shfl_xor_sync(0xffffffffu, tm1, 1));
        tm1 = fmaxf(tm1, __shfl_xor_sync(0xffffffffu, tm1, 2));
        float mn0 = fmaxf(m0, tm0), mn1 = fmaxf(m1, tm1);
        float sc0 = __expf(m0 - mn0), sc1 = __expf(m1 - mn1);
        m0 = mn0; m1 = mn1;

        float ls0 = 0.f, ls1 = 0.f;
#pragma unroll
        for (int j = 0; j < 4; j++) {
            float p0 = __expf(s[j][0] - m0);
            float p1 = __expf(s[j][1] - m0);
            float p2 = __expf(s[j][2] - m1);
            float p3 = __expf(s[j][3] - m1);
            ls0 += p0 + p1; ls1 += p2 + p3;
            uint2 u0; u0.x = f2tf(p0); u0.y = f2tf(p1);
            uint2 u1; u1.x = f2tf(p2); u1.y = f2tf(p3);
            *(uint2*)(Pw + qr * PST + j * 8 + qc * 2)       = u0;
            *(uint2*)(Pw + (qr + 8) * PST + j * 8 + qc * 2) = u1;
        }
        ls0 += __shfl_xor_sync(0xffffffffu, ls0, 1);
        ls0 += __shfl_xor_sync(0xffffffffu, ls0, 2);
        ls1 += __shfl_xor_sync(0xffffffffu, ls1, 1);
        ls1 += __shfl_xor_sync(0xffffffffu, ls1, 2);
        l0 = l0 * sc0 + ls0;
        l1 = l1 * sc1 + ls1;
#pragma unroll
        for (int j = 0; j < 8; j++) {
            o[j][0] *= sc0; o[j][1] *= sc0; o[j][2] *= sc1; o[j][3] *= sc1;
        }
        __syncwarp();

#pragma unroll
        for (int kc = 0; kc < 4; kc++) {
            uint32_t a0 = Pw[qr * PST + kc * 8 + qc];
            uint32_t a1 = Pw[(qr + 8) * PST + kc * 8 + qc];
            uint32_t a2 = Pw[qr * PST + kc * 8 + qc + 4];
            uint32_t a3 = Pw[(qr + 8) * PST + kc * 8 + qc + 4];
#pragma unroll
            for (int j = 0; j < 8; j++) {
                uint32_t b0 = Vc[(kc * 8 + qc) * VST + j * 8 + qr];
                uint32_t b1 = Vc[(kc * 8 + qc + 4) * VST + j * 8 + qr];
                mma_tf32(o[j][0], o[j][1], o[j][2], o[j][3], a0, a1, a2, a3, b0, b1);
            }
        }
        __syncthreads();
    }

    float inv0 = 1.f / l0, inv1 = 1.f / l1;
    size_t r0 = (size_t)b * Ss + row0 + wrow + qr;
    size_t r1 = r0 + 8;
#pragma unroll
    for (int j = 0; j < 8; j++) {
        int c0 = h * 64 + j * 8 + qc * 2;
        *(float2*)(vals + r0 * Dd + c0) = make_float2(o[j][0] * inv0, o[j][1] * inv0);
        *(float2*)(vals + r1 * Dd + c0) = make_float2(o[j][2] * inv1, o[j][3] * inv1);
    }
}

// ---------------- host launch ----------------------------------------------
extern "C" void kernel_launch(void* const* d_in, const int* in_sizes, int n_in,
                              void* d_out, int out_size) {
    const float* x     = (const float*)d_in[0];
    const float* qkv_w = (const float*)d_in[1];
    const float* qkv_b = (const float*)d_in[2];
    const float* out_w = (const float*)d_in[3];
    const float* out_b = (const float*)d_in[4];
    const float* ln1_w = (const float*)d_in[5];
    const float* ln1_b = (const float*)d_in[6];
    const float* fc1_w = (const float*)d_in[7];
    const float* fc1_b = (const float*)d_in[8];
    const float* fc2_w = (const float*)d_in[9];
    const float* fc2_b = (const float*)d_in[10];
    const float* ln2_w = (const float*)d_in[11];
    const float* ln2_b = (const float*)d_in[12];

    float *xb, *hb, *qkvb, *vb, *fb, *pb;
    cudaGetSymbolAddress((void**)&xb,  g_x);
    cudaGetSymbolAddress((void**)&hb,  g_h);
    cudaGetSymbolAddress((void**)&qkvb,g_qkv);
    cudaGetSymbolAddress((void**)&vb,  g_vals);
    cudaGetSymbolAddress((void**)&fb,  g_ffn);
    cudaGetSymbolAddress((void**)&pb,  g_part);

    cudaFuncSetAttribute(flash_tf32, cudaFuncAttributeMaxDynamicSharedMemorySize, FLASH_SMEM);

    const int total = MTOK * Dd;
    const int redBlocks = (total / 4 + 255) / 256;

    for (int l = 0; l < Ll; l++) {
        const float* qw  = qkv_w + (size_t)l * Dd * D3;
        const float* qbb = qkv_b + (size_t)l * D3;
        const float* ow  = out_w + (size_t)l * Dd * Dd;
        const float* ob  = out_b + (size_t)l * Dd;
        const float* l1w = ln1_w + (size_t)l * Dd;
        const float* l1b = ln1_b + (size_t)l * Dd;
        const float* f1w = fc1_w + (size_t)l * Dd * Ii;
        const float* f1b = fc1_b + (size_t)l * Ii;
        const float* f2w = fc2_w + (size_t)l * Ii * Dd;
        const float* f2b = fc2_b + (size_t)l * Dd;
        const float* l2w = ln2_w + (size_t)l * Dd;
        const float* l2b = ln2_b + (size_t)l * Dd;

        const float* xin = (l == 0) ? x : xb;

        // 1. h = LN1(x) — standalone only for layer 0 (fused otherwise)
        if (l == 0)
            ln_kernel<<<MTOK, 256>>>(xin, l1w, l1b, hb);
        // 2. qkv = h @ qkv_w + qkv_b
        gemm_tf32<false, false, false><<<dim3(D3 / 128, MTOK / 128), 512>>>(
            MTOK, D3, Dd, hb, qw, qbb, nullptr, qkvb);
        // 3-5. fused attention
        flash_tf32<<<dim3(Ss / 64, Bb * Hh), 128, FLASH_SMEM>>>(qkvb, vb);
        // 6. out-proj split-K, then fused: x = xin + parts + bias; h = LN2(x)
        gemm_tf32<false, false, true><<<dim3(Dd / 128, MTOK / 128, 3), 512>>>(
            MTOK, Dd, Dd, vb, ow, nullptr, nullptr, pb);
        reduce_ln_kernel<3><<<MTOK, 256>>>(pb, ob, xin, l2w, l2b, xb, hb);
        // 7. ffn = gelu(h @ fc1_w + fc1_b)
        gemm_tf32<true, false, false><<<dim3(Ii / 128, MTOK / 128), 512>>>(
            MTOK, Ii, Dd, hb, f1w, f1b, nullptr, fb);
        // 8. fc2 split-K, then fused reduce (+ LN1 of next layer, except last)
        gemm_tf32<false, false, true><<<dim3(Dd / 128, MTOK / 128, 3), 512>>>(
            MTOK, Dd, Ii, fb, f2w, nullptr, nullptr, pb);
        if (l < Ll - 1) {
            const float* n1w = ln1_w + (size_t)(l + 1) * Dd;
            const float* n1b = ln1_b + (size_t)(l + 1) * Dd;
            reduce_ln_kernel<3><<<MTOK, 256>>>(pb, f2b, xb, n1w, n1b, xb, hb);
        } else {
            reduce_kernel<3><<<redBlocks, 256>>>(pb, f2b, xb, (float*)d_out, Dd, total);
        }
    }
}

// round 16
// speedup vs baseline: 1.0329x; 1.0149x over previous
#include <cuda_runtime.h>
#include <math.h>
#include <stdint.h>

// Problem constants
#define Bb   2
#define Ss   2048
#define Dd   768
#define Hh   12
#define Ii   3072
#define Ll   4
#define MTOK (Bb*Ss)          // 4096 tokens
#define D3   (3*Dd)           // 2304

// per-layer tf32-converted weight offsets (floats)
#define WT_QKV  0
#define WT_OUT  1769472
#define WT_FC1  2359296
#define WT_FC2  4718592
#define WT_LAYER 7077888

// ---------------- scratch buffers (device globals; no allocation) -----------
__device__ float g_x   [MTOK*Dd];
__device__ float g_h   [MTOK*Dd];
__device__ float g_qkv [MTOK*D3];
__device__ float g_vals[MTOK*Dd];
__device__ float g_ffn [MTOK*Ii];
__device__ float g_part[3*MTOK*Dd];            // split-K partials
__device__ float g_wt  [(size_t)Ll*WT_LAYER];  // tf32-rounded weights (113 MB)

// ---------------- tf32 / async helpers ---------------------------------------
__device__ __forceinline__ uint32_t f2tf(float x) {
    uint32_t r; asm("cvt.rna.tf32.f32 %0, %1;" : "=r"(r) : "f"(x)); return r;
}
__device__ __forceinline__ float f2tff(float x) {
    return __uint_as_float(f2tf(x));
}
__device__ __forceinline__ void mma_tf32(float& c0, float& c1, float& c2, float& c3,
                                         uint32_t a0, uint32_t a1, uint32_t a2, uint32_t a3,
                                         uint32_t b0, uint32_t b1) {
    asm volatile("mma.sync.aligned.m16n8k8.row.col.f32.tf32.tf32.f32 "
                 "{%0,%1,%2,%3}, {%4,%5,%6,%7}, {%8,%9}, {%0,%1,%2,%3};"
                 : "+f"(c0), "+f"(c1), "+f"(c2), "+f"(c3)
                 : "r"(a0), "r"(a1), "r"(a2), "r"(a3), "r"(b0), "r"(b1));
}
__device__ __forceinline__ uint32_t smem_u32(const void* p) {
    uint32_t a;
    asm("{ .reg .u64 t; cvta.to.shared.u64 t, %1; cvt.u32.u64 %0, t; }" : "=r"(a) : "l"(p));
    return a;
}
__device__ __forceinline__ void cp_async16(uint32_t saddr, const void* gptr) {
    asm volatile("cp.async.cg.shared.global [%0], [%1], 16;" :: "r"(saddr), "l"(gptr) : "memory");
}
#define CP_COMMIT() asm volatile("cp.async.commit_group;" ::: "memory")
#define CP_WAIT(n)  asm volatile("cp.async.wait_group %0;" :: "n"(n) : "memory")

// ---------------- weight pre-conversion: fp32 -> tf32-rounded fp32 -----------
__global__ void wconv_kernel(const float4* __restrict__ in, float4* __restrict__ out, int n4) {
    int i = blockIdx.x * blockDim.x + threadIdx.x;
    if (i >= n4) return;
    float4 v = in[i];
    float4 o;
    o.x = f2tff(v.x); o.y = f2tff(v.y); o.z = f2tff(v.z); o.w = f2tff(v.w);
    out[i] = o;
}

// ---------------- LayerNorm (standalone: only layer 0's LN1) -----------------
// hout is tf32-pre-rounded (GEMM A operand).
__global__ void ln_kernel(const float* __restrict__ x,
                          const float* __restrict__ w,
                          const float* __restrict__ b,
                          float* __restrict__ out) {
    int row = blockIdx.x;
    const float* xr = x + (size_t)row * Dd;
    float v[3];
    float lsum = 0.f, lsq = 0.f;
#pragma unroll
    for (int i = 0; i < 3; i++) {
        v[i] = xr[threadIdx.x + i * 256];
        lsum += v[i];
        lsq  += v[i] * v[i];
    }
    __shared__ float s1[256], s2[256];
    s1[threadIdx.x] = lsum; s2[threadIdx.x] = lsq;
    __syncthreads();
    for (int off = 128; off > 0; off >>= 1) {
        if (threadIdx.x < off) {
            s1[threadIdx.x] += s1[threadIdx.x + off];
            s2[threadIdx.x] += s2[threadIdx.x + off];
        }
        __syncthreads();
    }
    float mean = s1[0] * (1.f / 768.f);
    float var  = s2[0] * (1.f / 768.f) - mean * mean;
    float inv  = rsqrtf(var + 1e-5f);
#pragma unroll
    for (int i = 0; i < 3; i++) {
        int c = threadIdx.x + i * 256;
        out[(size_t)row * Dd + c] = f2tff((v[i] - mean) * inv * w[c] + b[c]);
    }
}

// ---------------- fused split-K reduce + residual + LayerNorm ----------------
// x = res + bias + sum(parts) (full fp32); h = tf32(LN(x)).
template<int NS>
__global__ void reduce_ln_kernel(const float* __restrict__ parts,
                                 const float* __restrict__ bias,
                                 const float* __restrict__ res,
                                 const float* __restrict__ lnw,
                                 const float* __restrict__ lnb,
                                 float* __restrict__ xout,
                                 float* __restrict__ hout) {
    int row = blockIdx.x;
    size_t base = (size_t)row * Dd;
    float v[3];
    float lsum = 0.f, lsq = 0.f;
#pragma unroll
    for (int i = 0; i < 3; i++) {
        int c = threadIdx.x + i * 256;
        float s = res[base + c] + bias[c];
#pragma unroll
        for (int z = 0; z < NS; z++)
            s += parts[(size_t)z * (MTOK * Dd) + base + c];
        v[i] = s;
        lsum += s;
        lsq  += s * s;
    }
    __shared__ float s1[256], s2[256];
    s1[threadIdx.x] = lsum; s2[threadIdx.x] = lsq;
    __syncthreads();
    for (int off = 128; off > 0; off >>= 1) {
        if (threadIdx.x < off) {
            s1[threadIdx.x] += s1[threadIdx.x + off];
            s2[threadIdx.x] += s2[threadIdx.x + off];
        }
        __syncthreads();
    }
    float mean = s1[0] * (1.f / 768.f);
    float var  = s2[0] * (1.f / 768.f) - mean * mean;
    float inv  = rsqrtf(var + 1e-5f);
#pragma unroll
    for (int i = 0; i < 3; i++) {
        int c = threadIdx.x + i * 256;
        xout[base + c] = v[i];
        hout[base + c] = f2tff((v[i] - mean) * inv * lnw[c] + lnb[c]);
    }
}

// ---------------- plain split-K reduce (last layer's FFN -> d_out) -----------
template<int NS>
__global__ void reduce_kernel(const float* __restrict__ parts,
                              const float* __restrict__ bias,
                              const float* __restrict__ res,
                              float* __restrict__ out, int N, int total) {
    int i = blockIdx.x * blockDim.x + threadIdx.x;
    int i4 = i * 4;
    if (i4 >= total) return;
    int col = i4 % N;
    float4 b = *(const float4*)(bias + col);
    float4 r = *(const float4*)(res + i4);
    float4 s = make_float4(r.x + b.x, r.y + b.y, r.z + b.z, r.w + b.w);
#pragma unroll
    for (int z = 0; z < NS; z++) {
        float4 p = *(const float4*)(parts + (size_t)z * total + i4);
        s.x += p.x; s.y += p.y; s.z += p.z; s.w += p.w;
    }
    *(float4*)(out + i4) = s;
}

// ---------------- TF32 GEMM: cp.async double-buffered, pre-rounded operands --
// BM=BN=128, BK=16, 512 thr / 16 warps. A smem [128][20], B smem [16][136].
// A and B are already exact tf32 values -> no per-fragment rounding needed.
// ROUND: round output to tf32 in epilogue (when it feeds another GEMM/flash).
#define AST 20
#define BST 136
template<bool GELU, bool SPLITK, bool ROUND>
__global__ __launch_bounds__(512, 2) void gemm_tf32(int M, int N, int K,
                               const float* __restrict__ A,
                               const float* __restrict__ Bm,
                               const float* __restrict__ bias,
                               float* __restrict__ C) {
    __shared__ uint32_t As[2][128][AST];
    __shared__ uint32_t Bs[2][16][BST];
    int tid  = threadIdx.x;
    int lane = tid & 31, wid = tid >> 5;
    int wm = (wid >> 2) * 32;
    int wn = (wid & 3) * 32;
    int qr = lane >> 2, qc = lane & 3;
    int row0 = blockIdx.y * 128, col0 = blockIdx.x * 128;

    int Ks = K;
    const float* Ab = A;
    const float* Bb2 = Bm;
    if (SPLITK) {
        Ks = K / gridDim.z;
        int koff = blockIdx.z * Ks;
        Ab  = A + koff;
        Bb2 = Bm + (size_t)koff * N;
        C   = C + (size_t)blockIdx.z * M * N;
    }

    int aRow = tid >> 2, aSeg = (tid & 3) * 4;
    int bRow = tid >> 5, bSeg = (tid & 31) * 4;
    uint32_t sA = smem_u32(As), sB = smem_u32(Bs);
    const float* aG = Ab + (size_t)(row0 + aRow) * K + aSeg;
    const float* bG = Bb2 + (size_t)bRow * N + col0 + bSeg;

    float acc[2][4][4] = {};

    const int nT = Ks / 16;
    cp_async16(sA + ((0 * 128 + aRow) * AST + aSeg) * 4, aG);
    cp_async16(sB + ((0 * 16 + bRow) * BST + bSeg) * 4, bG);
    CP_COMMIT();

    for (int t = 0; t < nT; t++) {
        int cur = t & 1;
        if (t + 1 < nT) {
            int buf = cur ^ 1;
            int k0 = (t + 1) * 16;
            cp_async16(sA + ((buf * 128 + aRow) * AST + aSeg) * 4, aG + k0);
            cp_async16(sB + ((buf * 16 + bRow) * BST + bSeg) * 4, bG + (size_t)k0 * N);
            CP_COMMIT();
            CP_WAIT(1);
        } else {
            CP_WAIT(0);
        }
        __syncthreads();
#pragma unroll
        for (int ks = 0; ks < 16; ks += 8) {
            uint32_t af[2][4], bf[4][2];
#pragma unroll
            for (int i = 0; i < 2; i++) {
                int m = wm + i * 16 + qr;
                af[i][0] = As[cur][m][ks + qc];
                af[i][1] = As[cur][m + 8][ks + qc];
                af[i][2] = As[cur][m][ks + qc + 4];
                af[i][3] = As[cur][m + 8][ks + qc + 4];
            }
#pragma unroll
            for (int j = 0; j < 4; j++) {
                int n = wn + j * 8 + qr;
                bf[j][0] = Bs[cur][ks + qc][n];
                bf[j][1] = Bs[cur][ks + qc + 4][n];
            }
#pragma unroll
            for (int i = 0; i < 2; i++)
#pragma unroll
                for (int j = 0; j < 4; j++)
                    mma_tf32(acc[i][j][0], acc[i][j][1], acc[i][j][2], acc[i][j][3],
                             af[i][0], af[i][1], af[i][2], af[i][3],
                             bf[j][0], bf[j][1]);
        }
        __syncthreads();
    }
#pragma unroll
    for (int i = 0; i < 2; i++) {
        int r0 = row0 + wm + i * 16 + qr;
        int r1 = r0 + 8;
#pragma unroll
        for (int j = 0; j < 4; j++) {
            int c0 = col0 + wn + j * 8 + qc * 2;
            float v0 = acc[i][j][0];
            float v1 = acc[i][j][1];
            float v2 = acc[i][j][2];
            float v3 = acc[i][j][3];
            if (!SPLITK) {
                v0 += bias[c0]; v1 += bias[c0 + 1];
                v2 += bias[c0]; v3 += bias[c0 + 1];
                if (GELU) {
                    v0 = 0.5f * v0 * (1.0f + erff(v0 * 0.70710678f));
                    v1 = 0.5f * v1 * (1.0f + erff(v1 * 0.70710678f));
                    v2 = 0.5f * v2 * (1.0f + erff(v2 * 0.70710678f));
                    v3 = 0.5f * v3 * (1.0f + erff(v3 * 0.70710678f));
                }
                if (ROUND) {
                    v0 = f2tff(v0); v1 = f2tff(v1);
                    v2 = f2tff(v2); v3 = f2tff(v3);
                }
            }
            *(float2*)(C + (size_t)r0 * N + c0) = make_float2(v0, v1);
            *(float2*)(C + (size_t)r1 * N + c0) = make_float2(v2, v3);
        }
    }
}

// ---------------- fused flash attention: cp.async double-buffered KV ---------
// qkv input is tf32-pre-rounded; K/V used raw (exact), Q rescaled (exact).
// Output vals pre-rounded to tf32 (feeds out-proj GEMM).
#define TSV  32
#define KST  68
#define VST  72
#define PST  68
#define FLASH_SMEM ((2*TSV*KST + 2*TSV*VST + 4*16*PST) * 4)   // 53,248 B

__global__ __launch_bounds__(128, 4) void flash_tf32(const float* __restrict__ qkv,
                                                     float* __restrict__ vals) {
    extern __shared__ uint32_t sm[];
    uint32_t* Ks   = sm;
    uint32_t* Vs   = sm + 2 * TSV * KST;
    uint32_t* Pall = Vs + 2 * TSV * VST;

    int tid = threadIdx.x, lane = tid & 31, wid = tid >> 5;
    int qr = lane >> 2, qc = lane & 3;
    int z = blockIdx.y, b = z / Hh, h = z - b * Hh;
    const float* Qb = qkv + (size_t)b * Ss * D3 + h * 192;
    const float* Kb = Qb + 64;
    const float* Vb = Qb + 128;
    int row0 = blockIdx.x * 64;
    uint32_t* Pw = Pall + wid * 16 * PST;
    int wrow = wid * 16;

    uint32_t sKs = smem_u32(Ks), sVs = smem_u32(Vs);

    {
#pragma unroll
        for (int k = 0; k < 4; k++) {
            int i = tid + k * 128;
            int t = i >> 4, d = (i & 15) << 2;
            cp_async16(sKs + (t * KST + d) * 4, Kb + (size_t)t * D3 + d);
            cp_async16(sVs + (t * VST + d) * 4, Vb + (size_t)t * D3 + d);
        }
        CP_COMMIT();
    }

    for (int i = tid; i < 1024; i += 128) {
        int t = i >> 4, d = (i & 15) << 2;
        float4 q4 = *(const float4*)(Qb + (size_t)(row0 + t) * D3 + d);
        uint32_t* dst = Pall + t * PST + d;
        dst[0] = f2tf(q4.x * 0.125f);
        dst[1] = f2tf(q4.y * 0.125f);
        dst[2] = f2tf(q4.z * 0.125f);
        dst[3] = f2tf(q4.w * 0.125f);
    }
    __syncthreads();
    uint32_t qa[8][4];
#pragma unroll
    for (int kc = 0; kc < 8; kc++) {
        qa[kc][0] = Pall[(wrow + qr)     * PST + kc * 8 + qc];
        qa[kc][1] = Pall[(wrow + qr + 8) * PST + kc * 8 + qc];
        qa[kc][2] = Pall[(wrow + qr)     * PST + kc * 8 + qc + 4];
        qa[kc][3] = Pall[(wrow + qr + 8) * PST + kc * 8 + qc + 4];
    }
    __syncthreads();

    float m0 = -1e30f, m1 = -1e30f, l0 = 0.f, l1 = 0.f;
    float o[8][4] = {};

    const int NIT = Ss / TSV;   // 64
    for (int it = 0; it < NIT; it++) {
        int cur = it & 1;
        if (it + 1 < NIT) {
            int kv = (it + 1) * TSV;
            int buf = cur ^ 1;
#pragma unroll
            for (int k = 0; k < 4; k++) {
                int i = tid + k * 128;
                int t = i >> 4, d = (i & 15) << 2;
                cp_async16(sKs + (buf * TSV * KST + t * KST + d) * 4,
                           Kb + (size_t)(kv + t) * D3 + d);
                cp_async16(sVs + (buf * TSV * VST + t * VST + d) * 4,
                           Vb + (size_t)(kv + t) * D3 + d);
            }
            CP_COMMIT();
            CP_WAIT(1);
        } else {
            CP_WAIT(0);
        }
        __syncthreads();
        uint32_t* Kc = Ks + cur * TSV * KST;
        uint32_t* Vc = Vs + cur * TSV * VST;

        float s[4][4];
#pragma unroll
        for (int j = 0; j < 4; j++) {
            s[j][0] = s[j][1] = s[j][2] = s[j][3] = 0.f;
#pragma unroll
            for (int kc = 0; kc < 8; kc++) {
                uint32_t b0 = Kc[(j * 8 + qr) * KST + kc * 8 + qc];
                uint32_t b1 = Kc[(j * 8 + qr) * KST + kc * 8 + qc + 4];
                mma_tf32(s[j][0], s[j][1], s[j][2], s[j][3],
                         qa[kc][0], qa[kc][1], qa[kc][2], qa[kc][3], b0, b1);
            }
        }

        float tm0 = -1e30f, tm1 = -1e30f;
#pragma unroll
        for (int j = 0; j < 4; j++) {
            tm0 = fmaxf(tm0, fmaxf(s[j][0], s[j][1]));
            tm1 = fmaxf(tm1, fmaxf(s[j][2], s[j][3]));
        }
        tm0 = fmaxf(tm0, __shfl_xor_sync(0xffffffffu, tm0, 1));
        tm0 = fmaxf(tm0, __shfl_xor_sync(0xffffffffu, tm0, 2));
        tm1 = fmaxf(tm1, __shfl_xor_sync(0xffffffffu, tm1, 1));
        tm1 = fmaxf(tm1, __shfl_xor_sync(0xffffffffu, tm1, 2));
        float mn0 = fmaxf(m0, tm0), mn1 = fmaxf(m1, tm1);
        float sc0 = __expf(m0 - mn0), sc1 = __expf(m1 - mn1);
        m0 = mn0; m1 = mn1;

        float ls0 = 0.f, ls1 = 0.f;
#pragma unroll
        for (int j = 0; j < 4; j++) {
            float p0 = __expf(s[j][0] - m0);
            float p1 = __expf(s[j][1] - m0);
            float p2 = __expf(s[j][2] - m1);
            float p3 = __expf(s[j][3] - m1);
            ls0 += p0 + p1; ls1 += p2 + p3;
            uint2 u0; u0.x = f2tf(p0); u0.y = f2tf(p1);
            uint2 u1; u1.x = f2tf(p2); u1.y = f2tf(p3);
            *(uint2*)(Pw + qr * PST + j * 8 + qc * 2)       = u0;
            *(uint2*)(Pw + (qr + 8) * PST + j * 8 + qc * 2) = u1;
        }
        ls0 += __shfl_xor_sync(0xffffffffu, ls0, 1);
        ls0 += __shfl_xor_sync(0xffffffffu, ls0, 2);
        ls1 += __shfl_xor_sync(0xffffffffu, ls1, 1);
        ls1 += __shfl_xor_sync(0xffffffffu, ls1, 2);
        l0 = l0 * sc0 + ls0;
        l1 = l1 * sc1 + ls1;
#pragma unroll
        for (int j = 0; j < 8; j++) {
            o[j][0] *= sc0; o[j][1] *= sc0; o[j][2] *= sc1; o[j][3] *= sc1;
        }
        __syncwarp();

#pragma unroll
        for (int kc = 0; kc < 4; kc++) {
            uint32_t a0 = Pw[qr * PST + kc * 8 + qc];
            uint32_t a1 = Pw[(qr + 8) * PST + kc * 8 + qc];
            uint32_t a2 = Pw[qr * PST + kc * 8 + qc + 4];
            uint32_t a3 = Pw[(qr + 8) * PST + kc * 8 + qc + 4];
#pragma unroll
            for (int j = 0; j < 8; j++) {
                uint32_t b0 = Vc[(kc * 8 + qc) * VST + j * 8 + qr];
                uint32_t b1 = Vc[(kc * 8 + qc + 4) * VST + j * 8 + qr];
                mma_tf32(o[j][0], o[j][1], o[j][2], o[j][3], a0, a1, a2, a3, b0, b1);
            }
        }
        __syncthreads();
    }

    float inv0 = 1.f / l0, inv1 = 1.f / l1;
    size_t r0 = (size_t)b * Ss + row0 + wrow + qr;
    size_t r1 = r0 + 8;
#pragma unroll
    for (int j = 0; j < 8; j++) {
        int c0 = h * 64 + j * 8 + qc * 2;
        *(float2*)(vals + r0 * Dd + c0) = make_float2(f2tff(o[j][0] * inv0), f2tff(o[j][1] * inv0));
        *(float2*)(vals + r1 * Dd + c0) = make_float2(f2tff(o[j][2] * inv1), f2tff(o[j][3] * inv1));
    }
}

// ---------------- host launch ----------------------------------------------
extern "C" void kernel_launch(void* const* d_in, const int* in_sizes, int n_in,
                              void* d_out, int out_size) {
    const float* x     = (const float*)d_in[0];
    const float* qkv_w = (const float*)d_in[1];
    const float* qkv_b = (const float*)d_in[2];
    const float* out_w = (const float*)d_in[3];
    const float* out_b = (const float*)d_in[4];
    const float* ln1_w = (const float*)d_in[5];
    const float* ln1_b = (const float*)d_in[6];
    const float* fc1_w = (const float*)d_in[7];
    const float* fc1_b = (const float*)d_in[8];
    const float* fc2_w = (const float*)d_in[9];
    const float* fc2_b = (const float*)d_in[10];
    const float* ln2_w = (const float*)d_in[11];
    const float* ln2_b = (const float*)d_in[12];

    float *xb, *hb, *qkvb, *vb, *fb, *pb, *wt;
    cudaGetSymbolAddress((void**)&xb,  g_x);
    cudaGetSymbolAddress((void**)&hb,  g_h);
    cudaGetSymbolAddress((void**)&qkvb,g_qkv);
    cudaGetSymbolAddress((void**)&vb,  g_vals);
    cudaGetSymbolAddress((void**)&fb,  g_ffn);
    cudaGetSymbolAddress((void**)&pb,  g_part);
    cudaGetSymbolAddress((void**)&wt,  g_wt);

    cudaFuncSetAttribute(flash_tf32, cudaFuncAttributeMaxDynamicSharedMemorySize, FLASH_SMEM);

    const int total = MTOK * Dd;
    const int redBlocks = (total / 4 + 255) / 256;

    // one-time (per replay) weight pre-rounding to tf32
    for (int l = 0; l < Ll; l++) {
        float* base = wt + (size_t)l * WT_LAYER;
        int nq = Dd * D3 / 4, no = Dd * Dd / 4, nf = Dd * Ii / 4;
        wconv_kernel<<<(nq + 255) / 256, 256>>>(
            (const float4*)(qkv_w + (size_t)l * Dd * D3), (float4*)(base + WT_QKV), nq);
        wconv_kernel<<<(no + 255) / 256, 256>>>(
            (const float4*)(out_w + (size_t)l * Dd * Dd), (float4*)(base + WT_OUT), no);
        wconv_kernel<<<(nf + 255) / 256, 256>>>(
            (const float4*)(fc1_w + (size_t)l * Dd * Ii), (float4*)(base + WT_FC1), nf);
        wconv_kernel<<<(nf + 255) / 256, 256>>>(
            (const float4*)(fc2_w + (size_t)l * Ii * Dd), (float4*)(base + WT_FC2), nf);
    }

    for (int l = 0; l < Ll; l++) {
        const float* wbase = wt + (size_t)l * WT_LAYER;
        const float* qbb = qkv_b + (size_t)l * D3;
        const float* ob  = out_b + (size_t)l * Dd;
        const float* l1w = ln1_w + (size_t)l * Dd;
        const float* l1b = ln1_b + (size_t)l * Dd;
        const float* f1b = fc1_b + (size_t)l * Ii;
        const float* f2b = fc2_b + (size_t)l * Dd;
        const float* l2w = ln2_w + (size_t)l * Dd;
        const float* l2b = ln2_b + (size_t)l * Dd;

        const float* xin = (l == 0) ? x : xb;

        // 1. h = tf32(LN1(x)) — standalone only for layer 0 (fused otherwise)
        if (l == 0)
            ln_kernel<<<MTOK, 256>>>(xin, l1w, l1b, hb);
        // 2. qkv = tf32(h @ qkv_w + qkv_b)
        gemm_tf32<false, false, true><<<dim3(D3 / 128, MTOK / 128), 512>>>(
            MTOK, D3, Dd, hb, wbase + WT_QKV, qbb, qkvb);
        // 3-5. fused attention -> tf32 vals
        flash_tf32<<<dim3(Ss / 64, Bb * Hh), 128, FLASH_SMEM>>>(qkvb, vb);
        // 6. out-proj split-K, then fused: x = xin + parts + bias; h = tf32(LN2(x))
        gemm_tf32<false, true, false><<<dim3(Dd / 128, MTOK / 128, 3), 512>>>(
            MTOK, Dd, Dd, vb, wbase + WT_OUT, nullptr, pb);
        reduce_ln_kernel<3><<<MTOK, 256>>>(pb, ob, xin, l2w, l2b, xb, hb);
        // 7. ffn = tf32(gelu(h @ fc1_w + fc1_b))
        gemm_tf32<true, false, true><<<dim3(Ii / 128, MTOK / 128), 512>>>(
            MTOK, Ii, Dd, hb, wbase + WT_FC1, f1b, fb);
        // 8. fc2 split-K, then fused reduce (+ next layer's LN1, except last)
        gemm_tf32<false, true, false><<<dim3(Dd / 128, MTOK / 128, 3), 512>>>(
            MTOK, Dd, Ii, fb, wbase + WT_FC2, nullptr, pb);
        if (l < Ll - 1) {
            const float* n1w = ln1_w + (size_t)(l + 1) * Dd;
            const float* n1b = ln1_b + (size_t)(l + 1) * Dd;
            reduce_ln_kernel<3><<<MTOK, 256>>>(pb, f2b, xb, n1w, n1b, xb, hb);
        } else {
            reduce_kernel<3><<<redBlocks, 256>>>(pb, f2b, xb, (float*)d_out, Dd, total);
        }
    }
}

// round 17
// speedup vs baseline: 1.0435x; 1.0103x over previous
#include <cuda_runtime.h>
#include <math.h>
#include <stdint.h>

// Problem constants
#define Bb   2
#define Ss   2048
#define Dd   768
#define Hh   12
#define Ii   3072
#define Ll   4
#define MTOK (Bb*Ss)          // 4096 tokens
#define D3   (3*Dd)           // 2304

// ---------------- scratch buffers (device globals; no allocation) -----------
__device__ float g_x   [MTOK*Dd];
__device__ float g_h   [MTOK*Dd];
__device__ float g_qkv [MTOK*D3];
__device__ float g_vals[MTOK*Dd];
__device__ float g_ffn [MTOK*Ii];
__device__ float g_part[3*MTOK*Dd];            // split-K partials

// ---------------- tf32 / async helpers ---------------------------------------
__device__ __forceinline__ uint32_t f2tf(float x) {
    uint32_t r; asm("cvt.rna.tf32.f32 %0, %1;" : "=r"(r) : "f"(x)); return r;
}
__device__ __forceinline__ float f2tff(float x) {
    return __uint_as_float(f2tf(x));
}
// round-to-nearest emulation for raw fp32 operands: +half of truncated 13 bits
#define RN(u) ((u) + 0x1000u)
__device__ __forceinline__ void mma_tf32(float& c0, float& c1, float& c2, float& c3,
                                         uint32_t a0, uint32_t a1, uint32_t a2, uint32_t a3,
                                         uint32_t b0, uint32_t b1) {
    asm volatile("mma.sync.aligned.m16n8k8.row.col.f32.tf32.tf32.f32 "
                 "{%0,%1,%2,%3}, {%4,%5,%6,%7}, {%8,%9}, {%0,%1,%2,%3};"
                 : "+f"(c0), "+f"(c1), "+f"(c2), "+f"(c3)
                 : "r"(a0), "r"(a1), "r"(a2), "r"(a3), "r"(b0), "r"(b1));
}
__device__ __forceinline__ uint32_t smem_u32(const void* p) {
    uint32_t a;
    asm("{ .reg .u64 t; cvta.to.shared.u64 t, %1; cvt.u32.u64 %0, t; }" : "=r"(a) : "l"(p));
    return a;
}
__device__ __forceinline__ void cp_async16(uint32_t saddr, const void* gptr) {
    asm volatile("cp.async.cg.shared.global [%0], [%1], 16;" :: "r"(saddr), "l"(gptr) : "memory");
}
#define CP_COMMIT() asm volatile("cp.async.commit_group;" ::: "memory")
#define CP_WAIT(n)  asm volatile("cp.async.wait_group %0;" :: "n"(n) : "memory")

// ---------------- LayerNorm (standalone: only layer 0's LN1) -----------------
// hout is tf32-pre-rounded (GEMM A operand).
__global__ void ln_kernel(const float* __restrict__ x,
                          const float* __restrict__ w,
                          const float* __restrict__ b,
                          float* __restrict__ out) {
    int row = blockIdx.x;
    const float* xr = x + (size_t)row * Dd;
    float v[3];
    float lsum = 0.f, lsq = 0.f;
#pragma unroll
    for (int i = 0; i < 3; i++) {
        v[i] = xr[threadIdx.x + i * 256];
        lsum += v[i];
        lsq  += v[i] * v[i];
    }
    __shared__ float s1[256], s2[256];
    s1[threadIdx.x] = lsum; s2[threadIdx.x] = lsq;
    __syncthreads();
    for (int off = 128; off > 0; off >>= 1) {
        if (threadIdx.x < off) {
            s1[threadIdx.x] += s1[threadIdx.x + off];
            s2[threadIdx.x] += s2[threadIdx.x + off];
        }
        __syncthreads();
    }
    float mean = s1[0] * (1.f / 768.f);
    float var  = s2[0] * (1.f / 768.f) - mean * mean;
    float inv  = rsqrtf(var + 1e-5f);
#pragma unroll
    for (int i = 0; i < 3; i++) {
        int c = threadIdx.x + i * 256;
        out[(size_t)row * Dd + c] = f2tff((v[i] - mean) * inv * w[c] + b[c]);
    }
}

// ---------------- fused split-K reduce + residual + LayerNorm ----------------
// x = res + bias + sum(parts) (full fp32); h = tf32(LN(x)).
template<int NS>
__global__ void reduce_ln_kernel(const float* __restrict__ parts,
                                 const float* __restrict__ bias,
                                 const float* __restrict__ res,
                                 const float* __restrict__ lnw,
                                 const float* __restrict__ lnb,
                                 float* __restrict__ xout,
                                 float* __restrict__ hout) {
    int row = blockIdx.x;
    size_t base = (size_t)row * Dd;
    float v[3];
    float lsum = 0.f, lsq = 0.f;
#pragma unroll
    for (int i = 0; i < 3; i++) {
        int c = threadIdx.x + i * 256;
        float s = res[base + c] + bias[c];
#pragma unroll
        for (int z = 0; z < NS; z++)
            s += parts[(size_t)z * (MTOK * Dd) + base + c];
        v[i] = s;
        lsum += s;
        lsq  += s * s;
    }
    __shared__ float s1[256], s2[256];
    s1[threadIdx.x] = lsum; s2[threadIdx.x] = lsq;
    __syncthreads();
    for (int off = 128; off > 0; off >>= 1) {
        if (threadIdx.x < off) {
            s1[threadIdx.x] += s1[threadIdx.x + off];
            s2[threadIdx.x] += s2[threadIdx.x + off];
        }
        __syncthreads();
    }
    float mean = s1[0] * (1.f / 768.f);
    float var  = s2[0] * (1.f / 768.f) - mean * mean;
    float inv  = rsqrtf(var + 1e-5f);
#pragma unroll
    for (int i = 0; i < 3; i++) {
        int c = threadIdx.x + i * 256;
        xout[base + c] = v[i];
        hout[base + c] = f2tff((v[i] - mean) * inv * lnw[c] + lnb[c]);
    }
}

// ---------------- plain split-K reduce (last layer's FFN -> d_out) -----------
template<int NS>
__global__ void reduce_kernel(const float* __restrict__ parts,
                              const float* __restrict__ bias,
                              const float* __restrict__ res,
                              float* __restrict__ out, int N, int total) {
    int i = blockIdx.x * blockDim.x + threadIdx.x;
    int i4 = i * 4;
    if (i4 >= total) return;
    int col = i4 % N;
    float4 b = *(const float4*)(bias + col);
    float4 r = *(const float4*)(res + i4);
    float4 s = make_float4(r.x + b.x, r.y + b.y, r.z + b.z, r.w + b.w);
#pragma unroll
    for (int z = 0; z < NS; z++) {
        float4 p = *(const float4*)(parts + (size_t)z * total + i4);
        s.x += p.x; s.y += p.y; s.z += p.z; s.w += p.w;
    }
    *(float4*)(out + i4) = s;
}

// ---------------- TF32 GEMM: cp.async double-buffered ------------------------
// BM=BN=128, BK=16, 512 thr / 16 warps. A smem [128][20], B smem [16][136].
// A is tf32-pre-rounded by producers (exact); B is raw weights -> RN on the
// B fragments only (16 IADDs/iter). ROUND: tf32-round output in epilogue.
#define AST 20
#define BST 136
template<bool GELU, bool SPLITK, bool ROUND>
__global__ __launch_bounds__(512, 2) void gemm_tf32(int M, int N, int K,
                               const float* __restrict__ A,
                               const float* __restrict__ Bm,
                               const float* __restrict__ bias,
                               float* __restrict__ C) {
    __shared__ uint32_t As[2][128][AST];
    __shared__ uint32_t Bs[2][16][BST];
    int tid  = threadIdx.x;
    int lane = tid & 31, wid = tid >> 5;
    int wm = (wid >> 2) * 32;
    int wn = (wid & 3) * 32;
    int qr = lane >> 2, qc = lane & 3;
    int row0 = blockIdx.y * 128, col0 = blockIdx.x * 128;

    int Ks = K;
    const float* Ab = A;
    const float* Bb2 = Bm;
    if (SPLITK) {
        Ks = K / gridDim.z;
        int koff = blockIdx.z * Ks;
        Ab  = A + koff;
        Bb2 = Bm + (size_t)koff * N;
        C   = C + (size_t)blockIdx.z * M * N;
    }

    int aRow = tid >> 2, aSeg = (tid & 3) * 4;
    int bRow = tid >> 5, bSeg = (tid & 31) * 4;
    uint32_t sA = smem_u32(As), sB = smem_u32(Bs);
    const float* aG = Ab + (size_t)(row0 + aRow) * K + aSeg;
    const float* bG = Bb2 + (size_t)bRow * N + col0 + bSeg;

    float acc[2][4][4] = {};

    const int nT = Ks / 16;
    cp_async16(sA + ((0 * 128 + aRow) * AST + aSeg) * 4, aG);
    cp_async16(sB + ((0 * 16 + bRow) * BST + bSeg) * 4, bG);
    CP_COMMIT();

    for (int t = 0; t < nT; t++) {
        int cur = t & 1;
        if (t + 1 < nT) {
            int buf = cur ^ 1;
            int k0 = (t + 1) * 16;
            cp_async16(sA + ((buf * 128 + aRow) * AST + aSeg) * 4, aG + k0);
            cp_async16(sB + ((buf * 16 + bRow) * BST + bSeg) * 4, bG + (size_t)k0 * N);
            CP_COMMIT();
            CP_WAIT(1);
        } else {
            CP_WAIT(0);
        }
        __syncthreads();
#pragma unroll
        for (int ks = 0; ks < 16; ks += 8) {
            uint32_t af[2][4], bf[4][2];
#pragma unroll
            for (int i = 0; i < 2; i++) {
                int m = wm + i * 16 + qr;
                af[i][0] = As[cur][m][ks + qc];
                af[i][1] = As[cur][m + 8][ks + qc];
                af[i][2] = As[cur][m][ks + qc + 4];
                af[i][3] = As[cur][m + 8][ks + qc + 4];
            }
#pragma unroll
            for (int j = 0; j < 4; j++) {
                int n = wn + j * 8 + qr;
                bf[j][0] = RN(Bs[cur][ks + qc][n]);
                bf[j][1] = RN(Bs[cur][ks + qc + 4][n]);
            }
#pragma unroll
            for (int i = 0; i < 2; i++)
#pragma unroll
                for (int j = 0; j < 4; j++)
                    mma_tf32(acc[i][j][0], acc[i][j][1], acc[i][j][2], acc[i][j][3],
                             af[i][0], af[i][1], af[i][2], af[i][3],
                             bf[j][0], bf[j][1]);
        }
        __syncthreads();
    }
#pragma unroll
    for (int i = 0; i < 2; i++) {
        int r0 = row0 + wm + i * 16 + qr;
        int r1 = r0 + 8;
#pragma unroll
        for (int j = 0; j < 4; j++) {
            int c0 = col0 + wn + j * 8 + qc * 2;
            float v0 = acc[i][j][0];
            float v1 = acc[i][j][1];
            float v2 = acc[i][j][2];
            float v3 = acc[i][j][3];
            if (!SPLITK) {
                v0 += bias[c0]; v1 += bias[c0 + 1];
                v2 += bias[c0]; v3 += bias[c0 + 1];
                if (GELU) {
                    v0 = 0.5f * v0 * (1.0f + erff(v0 * 0.70710678f));
                    v1 = 0.5f * v1 * (1.0f + erff(v1 * 0.70710678f));
                    v2 = 0.5f * v2 * (1.0f + erff(v2 * 0.70710678f));
                    v3 = 0.5f * v3 * (1.0f + erff(v3 * 0.70710678f));
                }
                if (ROUND) {
                    v0 = f2tff(v0); v1 = f2tff(v1);
                    v2 = f2tff(v2); v3 = f2tff(v3);
                }
            }
            *(float2*)(C + (size_t)r0 * N + c0) = make_float2(v0, v1);
            *(float2*)(C + (size_t)r1 * N + c0) = make_float2(v2, v3);
        }
    }
}

// ---------------- fused flash attention: cp.async double-buffered KV ---------
// qkv input is tf32-pre-rounded; K/V used raw (exact), Q rescaled.
// Output vals pre-rounded to tf32 (feeds out-proj GEMM).
#define TSV  32
#define KST  68
#define VST  72
#define PST  68
#define FLASH_SMEM ((2*TSV*KST + 2*TSV*VST + 4*16*PST) * 4)   // 53,248 B

__global__ __launch_bounds__(128, 4) void flash_tf32(const float* __restrict__ qkv,
                                                     float* __restrict__ vals) {
    extern __shared__ uint32_t sm[];
    uint32_t* Ks   = sm;
    uint32_t* Vs   = sm + 2 * TSV * KST;
    uint32_t* Pall = Vs + 2 * TSV * VST;

    int tid = threadIdx.x, lane = tid & 31, wid = tid >> 5;
    int qr = lane >> 2, qc = lane & 3;
    int z = blockIdx.y, b = z / Hh, h = z - b * Hh;
    const float* Qb = qkv + (size_t)b * Ss * D3 + h * 192;
    const float* Kb = Qb + 64;
    const float* Vb = Qb + 128;
    int row0 = blockIdx.x * 64;
    uint32_t* Pw = Pall + wid * 16 * PST;
    int wrow = wid * 16;

    uint32_t sKs = smem_u32(Ks), sVs = smem_u32(Vs);

    {
#pragma unroll
        for (int k = 0; k < 4; k++) {
            int i = tid + k * 128;
            int t = i >> 4, d = (i & 15) << 2;
            cp_async16(sKs + (t * KST + d) * 4, Kb + (size_t)t * D3 + d);
            cp_async16(sVs + (t * VST + d) * 4, Vb + (size_t)t * D3 + d);
        }
        CP_COMMIT();
    }

    for (int i = tid; i < 1024; i += 128) {
        int t = i >> 4, d = (i & 15) << 2;
        float4 q4 = *(const float4*)(Qb + (size_t)(row0 + t) * D3 + d);
        uint32_t* dst = Pall + t * PST + d;
        dst[0] = f2tf(q4.x * 0.125f);
        dst[1] = f2tf(q4.y * 0.125f);
        dst[2] = f2tf(q4.z * 0.125f);
        dst[3] = f2tf(q4.w * 0.125f);
    }
    __syncthreads();
    uint32_t qa[8][4];
#pragma unroll
    for (int kc = 0; kc < 8; kc++) {
        qa[kc][0] = Pall[(wrow + qr)     * PST + kc * 8 + qc];
        qa[kc][1] = Pall[(wrow + qr + 8) * PST + kc * 8 + qc];
        qa[kc][2] = Pall[(wrow + qr)     * PST + kc * 8 + qc + 4];
        qa[kc][3] = Pall[(wrow + qr + 8) * PST + kc * 8 + qc + 4];
    }
    __syncthreads();

    float m0 = -1e30f, m1 = -1e30f, l0 = 0.f, l1 = 0.f;
    float o[8][4] = {};

    const int NIT = Ss / TSV;   // 64
    for (int it = 0; it < NIT; it++) {
        int cur = it & 1;
        if (it + 1 < NIT) {
            int kv = (it + 1) * TSV;
            int buf = cur ^ 1;
#pragma unroll
            for (int k = 0; k < 4; k++) {
                int i = tid + k * 128;
                int t = i >> 4, d = (i & 15) << 2;
                cp_async16(sKs + (buf * TSV * KST + t * KST + d) * 4,
                           Kb + (size_t)(kv + t) * D3 + d);
                cp_async16(sVs + (buf * TSV * VST + t * VST + d) * 4,
                           Vb + (size_t)(kv + t) * D3 + d);
            }
            CP_COMMIT();
            CP_WAIT(1);
        } else {
            CP_WAIT(0);
        }
        __syncthreads();
        uint32_t* Kc = Ks + cur * TSV * KST;
        uint32_t* Vc = Vs + cur * TSV * VST;

        float s[4][4];
#pragma unroll
        for (int j = 0; j < 4; j++) {
            s[j][0] = s[j][1] = s[j][2] = s[j][3] = 0.f;
#pragma unroll
            for (int kc = 0; kc < 8; kc++) {
                uint32_t b0 = Kc[(j * 8 + qr) * KST + kc * 8 + qc];
                uint32_t b1 = Kc[(j * 8 + qr) * KST + kc * 8 + qc + 4];
                mma_tf32(s[j][0], s[j][1], s[j][2], s[j][3],
                         qa[kc][0], qa[kc][1], qa[kc][2], qa[kc][3], b0, b1);
            }
        }

        float tm0 = -1e30f, tm1 = -1e30f;
#pragma unroll
        for (int j = 0; j < 4; j++) {
            tm0 = fmaxf(tm0, fmaxf(s[j][0], s[j][1]));
            tm1 = fmaxf(tm1, fmaxf(s[j][2], s[j][3]));
        }
        tm0 = fmaxf(tm0, __shfl_xor_sync(0xffffffffu, tm0, 1));
        tm0 = fmaxf(tm0, __shfl_xor_sync(0xffffffffu, tm0, 2));
        tm1 = fmaxf(tm1, __shfl_xor_sync(0xffffffffu, tm1, 1));
        tm1 = fmaxf(tm1, __shfl_xor_sync(0xffffffffu, tm1, 2));
        float mn0 = fmaxf(m0, tm0), mn1 = fmaxf(m1, tm1);
        float sc0 = __expf(m0 - mn0), sc1 = __expf(m1 - mn1);
        m0 = mn0; m1 = mn1;

        float ls0 = 0.f, ls1 = 0.f;
#pragma unroll
        for (int j = 0; j < 4; j++) {
            float p0 = __expf(s[j][0] - m0);
            float p1 = __expf(s[j][1] - m0);
            float p2 = __expf(s[j][2] - m1);
            float p3 = __expf(s[j][3] - m1);
            ls0 += p0 + p1; ls1 += p2 + p3;
            uint2 u0; u0.x = f2tf(p0); u0.y = f2tf(p1);
            uint2 u1; u1.x = f2tf(p2); u1.y = f2tf(p3);
            *(uint2*)(Pw + qr * PST + j * 8 + qc * 2)       = u0;
            *(uint2*)(Pw + (qr + 8) * PST + j * 8 + qc * 2) = u1;
        }
        ls0 += __shfl_xor_sync(0xffffffffu, ls0, 1);
        ls0 += __shfl_xor_sync(0xffffffffu, ls0, 2);
        ls1 += __shfl_xor_sync(0xffffffffu, ls1, 1);
        ls1 += __shfl_xor_sync(0xffffffffu, ls1, 2);
        l0 = l0 * sc0 + ls0;
        l1 = l1 * sc1 + ls1;
#pragma unroll
        for (int j = 0; j < 8; j++) {
            o[j][0] *= sc0; o[j][1] *= sc0; o[j][2] *= sc1; o[j][3] *= sc1;
        }
        __syncwarp();

#pragma unroll
        for (int kc = 0; kc < 4; kc++) {
            uint32_t a0 = Pw[qr * PST + kc * 8 + qc];
            uint32_t a1 = Pw[(qr + 8) * PST + kc * 8 + qc];
            uint32_t a2 = Pw[qr * PST + kc * 8 + qc + 4];
            uint32_t a3 = Pw[(qr + 8) * PST + kc * 8 + qc + 4];
#pragma unroll
            for (int j = 0; j < 8; j++) {
                uint32_t b0 = Vc[(kc * 8 + qc) * VST + j * 8 + qr];
                uint32_t b1 = Vc[(kc * 8 + qc + 4) * VST + j * 8 + qr];
                mma_tf32(o[j][0], o[j][1], o[j][2], o[j][3], a0, a1, a2, a3, b0, b1);
            }
        }
        __syncthreads();
    }

    float inv0 = 1.f / l0, inv1 = 1.f / l1;
    size_t r0 = (size_t)b * Ss + row0 + wrow + qr;
    size_t r1 = r0 + 8;
#pragma unroll
    for (int j = 0; j < 8; j++) {
        int c0 = h * 64 + j * 8 + qc * 2;
        *(float2*)(vals + r0 * Dd + c0) = make_float2(f2tff(o[j][0] * inv0), f2tff(o[j][1] * inv0));
        *(float2*)(vals + r1 * Dd + c0) = make_float2(f2tff(o[j][2] * inv1), f2tff(o[j][3] * inv1));
    }
}

// ---------------- host launch ----------------------------------------------
extern "C" void kernel_launch(void* const* d_in, const int* in_sizes, int n_in,
                              void* d_out, int out_size) {
    const float* x     = (const float*)d_in[0];
    const float* qkv_w = (const float*)d_in[1];
    const float* qkv_b = (const float*)d_in[2];
    const float* out_w = (const float*)d_in[3];
    const float* out_b = (const float*)d_in[4];
    const float* ln1_w = (const float*)d_in[5];
    const float* ln1_b = (const float*)d_in[6];
    const float* fc1_w = (const float*)d_in[7];
    const float* fc1_b = (const float*)d_in[8];
    const float* fc2_w = (const float*)d_in[9];
    const float* fc2_b = (const float*)d_in[10];
    const float* ln2_w = (const float*)d_in[11];
    const float* ln2_b = (const float*)d_in[12];

    float *xb, *hb, *qkvb, *vb, *fb, *pb;
    cudaGetSymbolAddress((void**)&xb,  g_x);
    cudaGetSymbolAddress((void**)&hb,  g_h);
    cudaGetSymbolAddress((void**)&qkvb,g_qkv);
    cudaGetSymbolAddress((void**)&vb,  g_vals);
    cudaGetSymbolAddress((void**)&fb,  g_ffn);
    cudaGetSymbolAddress((void**)&pb,  g_part);

    cudaFuncSetAttribute(flash_tf32, cudaFuncAttributeMaxDynamicSharedMemorySize, FLASH_SMEM);

    const int total = MTOK * Dd;
    const int redBlocks = (total / 4 + 255) / 256;

    for (int l = 0; l < Ll; l++) {
        const float* qw  = qkv_w + (size_t)l * Dd * D3;
        const float* qbb = qkv_b + (size_t)l * D3;
        const float* ow  = out_w + (size_t)l * Dd * Dd;
        const float* ob  = out_b + (size_t)l * Dd;
        const float* l1w = ln1_w + (size_t)l * Dd;
        const float* l1b = ln1_b + (size_t)l * Dd;
        const float* f1w = fc1_w + (size_t)l * Dd * Ii;
        const float* f1b = fc1_b + (size_t)l * Ii;
        const float* f2w = fc2_w + (size_t)l * Ii * Dd;
        const float* f2b = fc2_b + (size_t)l * Dd;
        const float* l2w = ln2_w + (size_t)l * Dd;
        const float* l2b = ln2_b + (size_t)l * Dd;

        const float* xin = (l == 0) ? x : xb;

        // 1. h = tf32(LN1(x)) — standalone only for layer 0 (fused otherwise)
        if (l == 0)
            ln_kernel<<<MTOK, 256>>>(xin, l1w, l1b, hb);
        // 2. qkv = tf32(h @ qkv_w + qkv_b)
        gemm_tf32<false, false, true><<<dim3(D3 / 128, MTOK / 128), 512>>>(
            MTOK, D3, Dd, hb, qw, qbb, qkvb);
        // 3-5. fused attention -> tf32 vals
        flash_tf32<<<dim3(Ss / 64, Bb * Hh), 128, FLASH_SMEM>>>(qkvb, vb);
        // 6. out-proj split-K, then fused: x = xin + parts + bias; h = tf32(LN2(x))
        gemm_tf32<false, true, false><<<dim3(Dd / 128, MTOK / 128, 3), 512>>>(
            MTOK, Dd, Dd, vb, ow, nullptr, pb);
        reduce_ln_kernel<3><<<MTOK, 256>>>(pb, ob, xin, l2w, l2b, xb, hb);
        // 7. ffn = tf32(gelu(h @ fc1_w + fc1_b))
        gemm_tf32<true, false, true><<<dim3(Ii / 128, MTOK / 128), 512>>>(
            MTOK, Ii, Dd, hb, f1w, f1b, fb);
        // 8. fc2 split-K, then fused reduce (+ next layer's LN1, except last)
        gemm_tf32<false, true, false><<<dim3(Dd / 128, MTOK / 128, 3), 512>>>(
            MTOK, Dd, Ii, fb, f2w, nullptr, pb);
        if (l < Ll - 1) {
            const float* n1w = ln1_w + (size_t)(l + 1) * Dd;
            const float* n1b = ln1_b + (size_t)(l + 1) * Dd;
            reduce_ln_kernel<3><<<MTOK, 256>>>(pb, f2b, xb, n1w, n1b, xb, hb);
        } else {
            reduce_kernel<3><<<redBlocks, 256>>>(pb, f2b, xb, (float*)d_out, Dd, total);
        }
    }
}